// round 11
// baseline (speedup 1.0000x reference)
#include <cuda_runtime.h>
#include <cuda_fp16.h>

#define NN 100000
#define NE 1600000
#define FD 128
#define NB 391            // ceil(NN / 256)
#define SA_STRIDE 136     // 128 + 8 halves pad -> conflict-free ldmatrix
#define SW_STRIDE 136
#define ROWS_PER_BLK 128  // 4 chunks of 32 rows; W staged once per block

// ---- scratch (static device arrays; no runtime alloc allowed) ----
static __device__ __half g_hh[(size_t)NN * FD];   // post-GEMM node features (fp16)
static __device__ __half g_zh[(size_t)NN * FD];   // relu(agg1*nd + b1) in fp16 (GEMM2 input)
static __device__ __half g_Wh1[FD * FD];          // W1 in fp16
static __device__ __half g_Wh2[FD * FD];          // W2 in fp16
static __device__ int    g_degout[NN];
static __device__ int    g_degin[NN];
static __device__ float  g_nsrc[NN];
static __device__ float  g_ndst[NN];
static __device__ int    g_rowptr[NN + 1];
static __device__ int    g_cursor[NN];
static __device__ int    g_csr[NE];               // src ids bucketed by dst
static __device__ int    g_bsum[512];
static __device__ float  g_a[NN];                 // dot(h2, Wp[:128])
static __device__ float  g_c[NN];                 // dot(h2, Wp[128:])

// ---- degree counting ----
__global__ void count_k(const int* __restrict__ src, const int* __restrict__ dst) {
    int e = blockIdx.x * blockDim.x + threadIdx.x;
    if (e < NE) {
        atomicAdd(&g_degout[src[e]], 1);
        atomicAdd(&g_degin[dst[e]], 1);
    }
}

__global__ void norm_k() {
    int i = blockIdx.x * blockDim.x + threadIdx.x;
    if (i < NN) {
        g_nsrc[i] = rsqrtf(fmaxf((float)g_degout[i], 1.0f));
        g_ndst[i] = rsqrtf(fmaxf((float)g_degin[i], 1.0f));
    }
}

// ---- W fp32 -> fp16 ----
__global__ void packW_k(const float* __restrict__ W, __half* __restrict__ Wh) {
    int i = blockIdx.x * blockDim.x + threadIdx.x;
    if (i < FD * FD) Wh[i] = __float2half(__ldg(W + i));
}

// ---- CSR build ----
__global__ void blocksum_k() {
    int i = blockIdx.x * 256 + threadIdx.x;
    int v = (i < NN) ? g_degin[i] : 0;
#pragma unroll
    for (int off = 16; off > 0; off >>= 1) v += __shfl_xor_sync(0xffffffffu, v, off);
    __shared__ int s[8];
    int lane = threadIdx.x & 31, wid = threadIdx.x >> 5;
    if (lane == 0) s[wid] = v;
    __syncthreads();
    if (threadIdx.x == 0) {
        int t = 0;
#pragma unroll
        for (int w = 0; w < 8; w++) t += s[w];
        g_bsum[blockIdx.x] = t;
    }
}

__global__ void scanbsum_k() {   // single block, exclusive scan of NB block sums
    __shared__ int sh[512];
    int t = threadIdx.x;
    int v = (t < NB) ? g_bsum[t] : 0;
    sh[t] = v;
    __syncthreads();
    for (int off = 1; off < 512; off <<= 1) {
        int a = (t >= off) ? sh[t - off] : 0;
        __syncthreads();
        sh[t] += a;
        __syncthreads();
    }
    if (t < NB) g_bsum[t] = sh[t] - v;   // exclusive
}

__global__ void rowptr_k() {
    int i = blockIdx.x * 256 + threadIdx.x;
    int lane = threadIdx.x & 31, wid = threadIdx.x >> 5;
    int v = (i < NN) ? g_degin[i] : 0;
    int incl = v;
#pragma unroll
    for (int off = 1; off < 32; off <<= 1) {
        int n = __shfl_up_sync(0xffffffffu, incl, off);
        if (lane >= off) incl += n;
    }
    __shared__ int ws[8];
    if (lane == 31) ws[wid] = incl;
    __syncthreads();
    if (threadIdx.x == 0) {
        int run = 0;
#pragma unroll
        for (int w = 0; w < 8; w++) { int t = ws[w]; ws[w] = run; run += t; }
    }
    __syncthreads();
    int excl = incl - v + ws[wid] + g_bsum[blockIdx.x];
    if (i < NN) {
        g_rowptr[i] = excl;
        g_cursor[i] = excl;
        if (i == NN - 1) g_rowptr[NN] = excl + v;
    }
}

__global__ void fill_k(const int* __restrict__ src, const int* __restrict__ dst) {
    int e = blockIdx.x * blockDim.x + threadIdx.x;
    if (e < NE) {
        int d = dst[e];
        int pos = atomicAdd(&g_cursor[d], 1);
        g_csr[pos] = src[e];
    }
}

// ---- HMMA helpers ----
__device__ __forceinline__ unsigned smem_u32(const void* p) {
    return (unsigned)__cvta_generic_to_shared(p);
}

__device__ __forceinline__ void ldsm_x4(unsigned& r0, unsigned& r1, unsigned& r2,
                                        unsigned& r3, unsigned addr) {
    asm volatile("ldmatrix.sync.aligned.m8n8.x4.shared.b16 {%0,%1,%2,%3}, [%4];"
                 : "=r"(r0), "=r"(r1), "=r"(r2), "=r"(r3) : "r"(addr));
}

__device__ __forceinline__ void ldsm_x4_t(unsigned& r0, unsigned& r1, unsigned& r2,
                                          unsigned& r3, unsigned addr) {
    asm volatile("ldmatrix.sync.aligned.m8n8.x4.trans.shared.b16 {%0,%1,%2,%3}, [%4];"
                 : "=r"(r0), "=r"(r1), "=r"(r2), "=r"(r3) : "r"(addr));
}

__device__ __forceinline__ void mma16816(float4& c, unsigned a0, unsigned a1,
                                         unsigned a2, unsigned a3,
                                         unsigned b0, unsigned b1) {
    asm volatile("mma.sync.aligned.m16n8k16.row.col.f32.f16.f16.f32 "
                 "{%0,%1,%2,%3}, {%4,%5,%6,%7}, {%8,%9}, {%0,%1,%2,%3};"
                 : "+f"(c.x), "+f"(c.y), "+f"(c.z), "+f"(c.w)
                 : "r"(a0), "r"(a1), "r"(a2), "r"(a3), "r"(b0), "r"(b1));
}

// ---- per-type row-fragment load (returns 8 fp16 cols packed in uint4) ----
__device__ __forceinline__ uint4 load_frag(const float* __restrict__ in, int gr, int c8) {
    uint4 st = make_uint4(0u, 0u, 0u, 0u);
    if (gr < NN) {
        float4 f0 = *reinterpret_cast<const float4*>(in + (size_t)gr * FD + c8);
        float4 f1 = *reinterpret_cast<const float4*>(in + (size_t)gr * FD + c8 + 4);
        __half2 h0 = __floats2half2_rn(f0.x, f0.y);
        __half2 h1 = __floats2half2_rn(f0.z, f0.w);
        __half2 h2 = __floats2half2_rn(f1.x, f1.y);
        __half2 h3 = __floats2half2_rn(f1.z, f1.w);
        st.x = *reinterpret_cast<unsigned*>(&h0);
        st.y = *reinterpret_cast<unsigned*>(&h1);
        st.z = *reinterpret_cast<unsigned*>(&h2);
        st.w = *reinterpret_cast<unsigned*>(&h3);
    }
    return st;
}

__device__ __forceinline__ uint4 load_frag(const __half* __restrict__ in, int gr, int c8) {
    if (gr < NN) return *reinterpret_cast<const uint4*>(in + (size_t)gr * FD + c8);
    return make_uint4(0u, 0u, 0u, 0u);
}

// ---- GEMM: out[i][:] = fp16( norm_src[i] * (in[i][:] @ W) ), tensor cores ----
// 256 thr / 8 warps, 128 rows in 4 chunks of 32; W staged once per block.
// A staging uses DEPTH-2 register prefetch (4x16B in flight per thread) so
// global loads for chunks i+1, i+2 overlap chunk i's MMA phase.
template <typename T>
__global__ __launch_bounds__(256) void gemm_k(const T* __restrict__ in,
                                              const __half* __restrict__ Wh,
                                              __half* __restrict__ out) {
    __shared__ __half sA[32 * SA_STRIDE];
    __shared__ __half sW[FD * SW_STRIDE];
    const int tid = threadIdx.x;
    const int blk0 = blockIdx.x * ROWS_PER_BLK;

    // stage W (fp16, already packed): 128 rows x 128 cols
    for (int i = tid; i < FD * 16; i += 256) {
        int r = i >> 4;
        int c8 = (i & 15) << 3;
        uint4 v = *reinterpret_cast<const uint4*>(Wh + r * FD + c8);
        *reinterpret_cast<uint4*>(&sW[r * SW_STRIDE + c8]) = v;
    }

    // per-thread A staging coords (2 fragments of 8 cols per chunk)
    const int r0s = tid >> 4;                 // rows 0..15
    const int c0s = (tid & 15) << 3;
    const int r1s = (tid + 256) >> 4;         // rows 16..31

    const int lane = tid & 31;
    const int wid = tid >> 5;
    const int m0 = (wid & 1) << 4;      // 0 or 16
    const int n0 = (wid >> 1) << 5;     // 0,32,64,96
    const int lm = lane >> 3;           // ldmatrix matrix id
    const int lr = lane & 7;            // row within matrix
    const int arow = m0 + ((lm & 1) << 3) + lr;
    const int koff = (lm >> 1) << 3;

    // prologue: prefetch chunks 0 and 1 (depth-2)
    uint4 cur0 = load_frag(in, blk0 + r0s, c0s);
    uint4 cur1 = load_frag(in, blk0 + r1s, c0s);
    uint4 nxt0 = load_frag(in, blk0 + 32 + r0s, c0s);
    uint4 nxt1 = load_frag(in, blk0 + 32 + r1s, c0s);

#pragma unroll
    for (int chunk = 0; chunk < 4; chunk++) {
        const int row0 = blk0 + chunk * 32;
        __syncthreads();   // sA free (prev readers done); also covers W stage
        *reinterpret_cast<uint4*>(&sA[r0s * SA_STRIDE + c0s]) = cur0;
        *reinterpret_cast<uint4*>(&sA[r1s * SA_STRIDE + c0s]) = cur1;
        cur0 = nxt0;
        cur1 = nxt1;
        if (chunk < 2) {   // prefetch chunk+2; overlaps MMA of chunks i, i+1
            nxt0 = load_frag(in, row0 + 64 + r0s, c0s);
            nxt1 = load_frag(in, row0 + 64 + r1s, c0s);
        }
        __syncthreads();

        float4 c[4];
#pragma unroll
        for (int j = 0; j < 4; j++) c[j] = make_float4(0.f, 0.f, 0.f, 0.f);

#pragma unroll
        for (int ks = 0; ks < 8; ks++) {
            int k0 = ks << 4;
            unsigned a0, a1, a2, a3;
            ldsm_x4(a0, a1, a2, a3, smem_u32(&sA[arow * SA_STRIDE + k0 + koff]));
#pragma unroll
            for (int j = 0; j < 2; j++) {
                int n = n0 + (j << 4);
                unsigned b0, b1, b2, b3;
                ldsm_x4_t(b0, b1, b2, b3,
                          smem_u32(&sW[(k0 + ((lm & 1) << 3) + lr) * SW_STRIDE + n + koff]));
                mma16816(c[2 * j],     a0, a1, a2, a3, b0, b1);
                mma16816(c[2 * j + 1], a0, a1, a2, a3, b2, b3);
            }
        }

        // epilogue: scale by norm_src, convert fp16, store
        const int rA = row0 + m0 + (lane >> 2);
        const int rB = rA + 8;
        float nsA = (rA < NN) ? g_nsrc[rA] : 0.f;
        float nsB = (rB < NN) ? g_nsrc[rB] : 0.f;
#pragma unroll
        for (int j = 0; j < 4; j++) {
            int col = n0 + (j << 3) + ((lane & 3) << 1);
            if (rA < NN) {
                __half2 h = __floats2half2_rn(c[j].x * nsA, c[j].y * nsA);
                *reinterpret_cast<__half2*>(out + (size_t)rA * FD + col) = h;
            }
            if (rB < NN) {
                __half2 h = __floats2half2_rn(c[j].z * nsB, c[j].w * nsB);
                *reinterpret_cast<__half2*>(out + (size_t)rB * FD + col) = h;
            }
        }
    }
}

// ---- warp-per-node CSR accumulate over fp16 rows (fp32 accum), unroll-4 ----
__device__ __forceinline__ float4 csr_accum(int node, int lane) {
    int beg = g_rowptr[node];
    int end = g_rowptr[node + 1];
    float4 acc = make_float4(0.f, 0.f, 0.f, 0.f);
    int j = beg;
    for (; j + 4 <= end; j += 4) {
        int s0 = __ldg(g_csr + j);
        int s1 = __ldg(g_csr + j + 1);
        int s2 = __ldg(g_csr + j + 2);
        int s3 = __ldg(g_csr + j + 3);
        uint2 u0 = *reinterpret_cast<const uint2*>(g_hh + (size_t)s0 * FD + lane * 4);
        uint2 u1 = *reinterpret_cast<const uint2*>(g_hh + (size_t)s1 * FD + lane * 4);
        uint2 u2 = *reinterpret_cast<const uint2*>(g_hh + (size_t)s2 * FD + lane * 4);
        uint2 u3 = *reinterpret_cast<const uint2*>(g_hh + (size_t)s3 * FD + lane * 4);
        float2 a0 = __half22float2(*reinterpret_cast<__half2*>(&u0.x));
        float2 b0 = __half22float2(*reinterpret_cast<__half2*>(&u0.y));
        float2 a1 = __half22float2(*reinterpret_cast<__half2*>(&u1.x));
        float2 b1 = __half22float2(*reinterpret_cast<__half2*>(&u1.y));
        float2 a2 = __half22float2(*reinterpret_cast<__half2*>(&u2.x));
        float2 b2 = __half22float2(*reinterpret_cast<__half2*>(&u2.y));
        float2 a3 = __half22float2(*reinterpret_cast<__half2*>(&u3.x));
        float2 b3 = __half22float2(*reinterpret_cast<__half2*>(&u3.y));
        acc.x += (a0.x + a1.x) + (a2.x + a3.x);
        acc.y += (a0.y + a1.y) + (a2.y + a3.y);
        acc.z += (b0.x + b1.x) + (b2.x + b3.x);
        acc.w += (b0.y + b1.y) + (b2.y + b3.y);
    }
    for (; j < end; j++) {
        int s = __ldg(g_csr + j);
        uint2 u = *reinterpret_cast<const uint2*>(g_hh + (size_t)s * FD + lane * 4);
        float2 a = __half22float2(*reinterpret_cast<__half2*>(&u.x));
        float2 b = __half22float2(*reinterpret_cast<__half2*>(&u.y));
        acc.x += a.x; acc.y += a.y; acc.z += b.x; acc.w += b.y;
    }
    return acc;
}

// ---- layer 1 aggregate, fused epilogue: z = fp16(relu(agg*nd + b1)) ----
__global__ __launch_bounds__(256) void gather1_k(const float* __restrict__ b1) {
    int w = (blockIdx.x * 256 + threadIdx.x) >> 5;
    if (w >= NN) return;
    int lane = threadIdx.x & 31;
    float4 acc = csr_accum(w, lane);
    float nd = g_ndst[w];
    float4 b = __ldg(reinterpret_cast<const float4*>(b1 + lane * 4));
    float ox = fmaxf(fmaf(acc.x, nd, b.x), 0.f);
    float oy = fmaxf(fmaf(acc.y, nd, b.y), 0.f);
    float oz = fmaxf(fmaf(acc.z, nd, b.z), 0.f);
    float ow = fmaxf(fmaf(acc.w, nd, b.w), 0.f);
    __half2 h01 = __floats2half2_rn(ox, oy);
    __half2 h23 = __floats2half2_rn(oz, ow);
    uint2 st;
    st.x = *reinterpret_cast<unsigned*>(&h01);
    st.y = *reinterpret_cast<unsigned*>(&h23);
    *reinterpret_cast<uint2*>(g_zh + (size_t)w * FD + lane * 4) = st;
}

// ---- layer 2 aggregate, fused link-predictor projection: a[i], c[i] ----
__global__ __launch_bounds__(256) void gather2_k(const float* __restrict__ b2,
                                                 const float* __restrict__ Wp) {
    int w = (blockIdx.x * 256 + threadIdx.x) >> 5;
    if (w >= NN) return;
    int lane = threadIdx.x & 31;
    float4 acc = csr_accum(w, lane);
    float nd = g_ndst[w];
    float4 b  = __ldg(reinterpret_cast<const float4*>(b2 + lane * 4));
    float4 w1 = __ldg(reinterpret_cast<const float4*>(Wp + lane * 4));
    float4 w2 = __ldg(reinterpret_cast<const float4*>(Wp + FD + lane * 4));
    float hx = fmaf(acc.x, nd, b.x);
    float hy = fmaf(acc.y, nd, b.y);
    float hz = fmaf(acc.z, nd, b.z);
    float hw = fmaf(acc.w, nd, b.w);
    float av = hx * w1.x + hy * w1.y + hz * w1.z + hw * w1.w;
    float cv = hx * w2.x + hy * w2.y + hz * w2.z + hw * w2.w;
#pragma unroll
    for (int off = 16; off > 0; off >>= 1) {
        av += __shfl_xor_sync(0xffffffffu, av, off);
        cv += __shfl_xor_sync(0xffffffffu, cv, off);
    }
    if (lane == 0) { g_a[w] = av; g_c[w] = cv; }
}

// ---- final per-edge score: sigmoid(a[src] + c[dst] + bp) ----
__global__ void edgescore_k(const int* __restrict__ src, const int* __restrict__ dst,
                            const float* __restrict__ bp, float* __restrict__ out) {
    int e = blockIdx.x * blockDim.x + threadIdx.x;
    if (e < NE) {
        float z = g_a[__ldg(src + e)] + g_c[__ldg(dst + e)] + __ldg(bp);
        out[e] = 1.0f / (1.0f + expf(-z));
    }
}

extern "C" void kernel_launch(void* const* d_in, const int* in_sizes, int n_in,
                              void* d_out, int out_size) {
    (void)in_sizes; (void)n_in; (void)out_size;
    const float* x  = (const float*)d_in[0];
    const float* W1 = (const float*)d_in[1];
    const float* b1 = (const float*)d_in[2];
    const float* W2 = (const float*)d_in[3];
    const float* b2 = (const float*)d_in[4];
    const float* Wp = (const float*)d_in[5];
    const float* bp = (const float*)d_in[6];
    const int* src  = (const int*)d_in[7];
    const int* dst  = (const int*)d_in[8];
    float* out = (float*)d_out;

    // persistent side stream + events (created once, on the uncaptured
    // correctness call; reused inside graph capture thereafter)
    static cudaStream_t s1 = nullptr;
    static cudaEvent_t evCount = nullptr, evSide = nullptr;
    if (s1 == nullptr) {
        cudaStreamCreateWithFlags(&s1, cudaStreamNonBlocking);
        cudaEventCreateWithFlags(&evCount, cudaEventDisableTiming);
        cudaEventCreateWithFlags(&evSide, cudaEventDisableTiming);
    }

    void *p_hh, *p_zh, *p_w1, *p_w2, *p_di, *p_do;
    cudaGetSymbolAddress(&p_hh, g_hh);
    cudaGetSymbolAddress(&p_zh, g_zh);
    cudaGetSymbolAddress(&p_w1, g_Wh1);
    cudaGetSymbolAddress(&p_w2, g_Wh2);
    cudaGetSymbolAddress(&p_di, g_degin);
    cudaGetSymbolAddress(&p_do, g_degout);

    cudaMemsetAsync(p_di, 0, sizeof(int) * NN);
    cudaMemsetAsync(p_do, 0, sizeof(int) * NN);

    // main stream: degrees -> norms -> W1 -> GEMM1
    count_k<<<(NE + 255) / 256, 256>>>(src, dst);
    cudaEventRecord(evCount, 0);

    norm_k<<<(NN + 255) / 256, 256>>>();
    packW_k<<<(FD * FD + 255) / 256, 256>>>(W1, (__half*)p_w1);
    gemm_k<float><<<(NN + ROWS_PER_BLK - 1) / ROWS_PER_BLK, 256>>>(
        x, (const __half*)p_w1, (__half*)p_hh);

    // side stream: CSR build + W2 pack, overlapped with GEMM1
    cudaStreamWaitEvent(s1, evCount, 0);
    blocksum_k<<<NB, 256, 0, s1>>>();
    scanbsum_k<<<1, 512, 0, s1>>>();
    rowptr_k<<<NB, 256, 0, s1>>>();
    fill_k<<<(NE + 255) / 256, 256, 0, s1>>>(src, dst);
    packW_k<<<(FD * FD + 255) / 256, 256, 0, s1>>>(W2, (__half*)p_w2);
    cudaEventRecord(evSide, s1);

    // join: gather1 needs GEMM1 (main) + CSR (side)
    cudaStreamWaitEvent(0, evSide, 0);

    // Layer 1 aggregate: z = fp16(relu(agg1 * norm_dst + b1))
    gather1_k<<<(NN * 32 + 255) / 256, 256>>>(b1);

    // Layer 2: h = fp16((z @ W2) * norm_src) ; fused gather -> per-node a, c
    gemm_k<__half><<<(NN + ROWS_PER_BLK - 1) / ROWS_PER_BLK, 256>>>(
        (const __half*)p_zh, (const __half*)p_w2, (__half*)p_hh);
    gather2_k<<<(NN * 32 + 255) / 256, 256>>>(b2, Wp);

    // Per-edge score
    edgescore_k<<<(NE + 255) / 256, 256>>>(src, dst, bp, out);
}

// round 12
// speedup vs baseline: 1.3946x; 1.3946x over previous
#include <cuda_runtime.h>
#include <cuda_fp16.h>

#define NN 100000
#define NE 1600000
#define FD 128
#define NB 391            // ceil(NN / 256)
#define SA_STRIDE 136     // 128 + 8 halves pad -> conflict-free ldmatrix
#define SW_STRIDE 136
#define ROWS_PER_BLK 128  // 2 chunks of 64 rows; W staged once per block

// ---- scratch (static device arrays; no runtime alloc allowed) ----
static __device__ __half g_hh[(size_t)NN * FD];   // post-GEMM node features (fp16)
static __device__ __half g_zh[(size_t)NN * FD];   // relu(agg1*nd + b1) in fp16 (GEMM2 input)
static __device__ __half g_Wh1[FD * FD];          // W1 in fp16
static __device__ __half g_Wh2[FD * FD];          // W2 in fp16
static __device__ int    g_degout[NN];
static __device__ int    g_degin[NN];
static __device__ float  g_nsrc[NN];
static __device__ float  g_ndst[NN];
static __device__ int    g_rowptr[NN + 1];
static __device__ int    g_cursor[NN];
static __device__ int    g_csr[NE];               // src ids bucketed by dst
static __device__ int    g_bsum[512];
static __device__ float  g_a[NN];                 // dot(h2, Wp[:128])
static __device__ float  g_c[NN];                 // dot(h2, Wp[128:])

// ---- degree counting ----
__global__ void count_k(const int* __restrict__ src, const int* __restrict__ dst) {
    int e = blockIdx.x * blockDim.x + threadIdx.x;
    if (e < NE) {
        atomicAdd(&g_degout[src[e]], 1);
        atomicAdd(&g_degin[dst[e]], 1);
    }
}

__global__ void norm_k() {
    int i = blockIdx.x * blockDim.x + threadIdx.x;
    if (i < NN) {
        g_nsrc[i] = rsqrtf(fmaxf((float)g_degout[i], 1.0f));
        g_ndst[i] = rsqrtf(fmaxf((float)g_degin[i], 1.0f));
    }
}

// ---- W fp32 -> fp16 ----
__global__ void packW_k(const float* __restrict__ W, __half* __restrict__ Wh) {
    int i = blockIdx.x * blockDim.x + threadIdx.x;
    if (i < FD * FD) Wh[i] = __float2half(__ldg(W + i));
}

// ---- CSR build ----
__global__ void blocksum_k() {
    int i = blockIdx.x * 256 + threadIdx.x;
    int v = (i < NN) ? g_degin[i] : 0;
#pragma unroll
    for (int off = 16; off > 0; off >>= 1) v += __shfl_xor_sync(0xffffffffu, v, off);
    __shared__ int s[8];
    int lane = threadIdx.x & 31, wid = threadIdx.x >> 5;
    if (lane == 0) s[wid] = v;
    __syncthreads();
    if (threadIdx.x == 0) {
        int t = 0;
#pragma unroll
        for (int w = 0; w < 8; w++) t += s[w];
        g_bsum[blockIdx.x] = t;
    }
}

__global__ void scanbsum_k() {   // single block, exclusive scan of NB block sums
    __shared__ int sh[512];
    int t = threadIdx.x;
    int v = (t < NB) ? g_bsum[t] : 0;
    sh[t] = v;
    __syncthreads();
    for (int off = 1; off < 512; off <<= 1) {
        int a = (t >= off) ? sh[t - off] : 0;
        __syncthreads();
        sh[t] += a;
        __syncthreads();
    }
    if (t < NB) g_bsum[t] = sh[t] - v;   // exclusive
}

__global__ void rowptr_k() {
    int i = blockIdx.x * 256 + threadIdx.x;
    int lane = threadIdx.x & 31, wid = threadIdx.x >> 5;
    int v = (i < NN) ? g_degin[i] : 0;
    int incl = v;
#pragma unroll
    for (int off = 1; off < 32; off <<= 1) {
        int n = __shfl_up_sync(0xffffffffu, incl, off);
        if (lane >= off) incl += n;
    }
    __shared__ int ws[8];
    if (lane == 31) ws[wid] = incl;
    __syncthreads();
    if (threadIdx.x == 0) {
        int run = 0;
#pragma unroll
        for (int w = 0; w < 8; w++) { int t = ws[w]; ws[w] = run; run += t; }
    }
    __syncthreads();
    int excl = incl - v + ws[wid] + g_bsum[blockIdx.x];
    if (i < NN) {
        g_rowptr[i] = excl;
        g_cursor[i] = excl;
        if (i == NN - 1) g_rowptr[NN] = excl + v;
    }
}

__global__ void fill_k(const int* __restrict__ src, const int* __restrict__ dst) {
    int e = blockIdx.x * blockDim.x + threadIdx.x;
    if (e < NE) {
        int d = dst[e];
        int pos = atomicAdd(&g_cursor[d], 1);
        g_csr[pos] = src[e];
    }
}

// ---- HMMA helpers ----
__device__ __forceinline__ unsigned smem_u32(const void* p) {
    return (unsigned)__cvta_generic_to_shared(p);
}

__device__ __forceinline__ void ldsm_x4(unsigned& r0, unsigned& r1, unsigned& r2,
                                        unsigned& r3, unsigned addr) {
    asm volatile("ldmatrix.sync.aligned.m8n8.x4.shared.b16 {%0,%1,%2,%3}, [%4];"
                 : "=r"(r0), "=r"(r1), "=r"(r2), "=r"(r3) : "r"(addr));
}

__device__ __forceinline__ void ldsm_x4_t(unsigned& r0, unsigned& r1, unsigned& r2,
                                          unsigned& r3, unsigned addr) {
    asm volatile("ldmatrix.sync.aligned.m8n8.x4.trans.shared.b16 {%0,%1,%2,%3}, [%4];"
                 : "=r"(r0), "=r"(r1), "=r"(r2), "=r"(r3) : "r"(addr));
}

__device__ __forceinline__ void mma16816(float4& c, unsigned a0, unsigned a1,
                                         unsigned a2, unsigned a3,
                                         unsigned b0, unsigned b1) {
    asm volatile("mma.sync.aligned.m16n8k16.row.col.f32.f16.f16.f32 "
                 "{%0,%1,%2,%3}, {%4,%5,%6,%7}, {%8,%9}, {%0,%1,%2,%3};"
                 : "+f"(c.x), "+f"(c.y), "+f"(c.z), "+f"(c.w)
                 : "r"(a0), "r"(a1), "r"(a2), "r"(a3), "r"(b0), "r"(b1));
}

// ---- per-type row-fragment load (returns 8 fp16 cols packed in uint4) ----
__device__ __forceinline__ uint4 load_frag(const float* __restrict__ in, int gr, int c8) {
    uint4 st = make_uint4(0u, 0u, 0u, 0u);
    if (gr < NN) {
        float4 f0 = *reinterpret_cast<const float4*>(in + (size_t)gr * FD + c8);
        float4 f1 = *reinterpret_cast<const float4*>(in + (size_t)gr * FD + c8 + 4);
        __half2 h0 = __floats2half2_rn(f0.x, f0.y);
        __half2 h1 = __floats2half2_rn(f0.z, f0.w);
        __half2 h2 = __floats2half2_rn(f1.x, f1.y);
        __half2 h3 = __floats2half2_rn(f1.z, f1.w);
        st.x = *reinterpret_cast<unsigned*>(&h0);
        st.y = *reinterpret_cast<unsigned*>(&h1);
        st.z = *reinterpret_cast<unsigned*>(&h2);
        st.w = *reinterpret_cast<unsigned*>(&h3);
    }
    return st;
}

__device__ __forceinline__ uint4 load_frag(const __half* __restrict__ in, int gr, int c8) {
    if (gr < NN) return *reinterpret_cast<const uint4*>(in + (size_t)gr * FD + c8);
    return make_uint4(0u, 0u, 0u, 0u);
}

// ---- GEMM: out[i][:] = fp16( norm_src[i] * (in[i][:] @ W) ), tensor cores ----
// 256 thr / 8 warps, 128 rows in 2 chunks of 64; W staged once per block.
// Each thread prefetches 4x16B for the next chunk during this chunk's MMA
// (big load burst -> DRAM overlap). Each warp computes TWO m=16 tiles per
// chunk sharing B fragments (halves ldmatrix.trans traffic).
template <typename T>
__global__ __launch_bounds__(256) void gemm_k(const T* __restrict__ in,
                                              const __half* __restrict__ Wh,
                                              __half* __restrict__ out) {
    __shared__ __half sA[64 * SA_STRIDE];
    __shared__ __half sW[FD * SW_STRIDE];
    const int tid = threadIdx.x;
    const int blk0 = blockIdx.x * ROWS_PER_BLK;

    // stage W (fp16, already packed): 128 rows x 128 cols
    for (int i = tid; i < FD * 16; i += 256) {
        int r = i >> 4;
        int c8 = (i & 15) << 3;
        uint4 v = *reinterpret_cast<const uint4*>(Wh + r * FD + c8);
        *reinterpret_cast<uint4*>(&sW[r * SW_STRIDE + c8]) = v;
    }

    // per-thread A staging coords: 4 fragments (64 rows x 16 col-groups)
    int rs[4], cs;
    cs = (tid & 15) << 3;
#pragma unroll
    for (int p = 0; p < 4; p++) rs[p] = (tid + p * 256) >> 4;

    const int lane = tid & 31;
    const int wid = tid >> 5;
    const int mA = (wid & 1) << 4;      // 0 or 16 (second tile at +32)
    const int n0 = (wid >> 1) << 5;     // 0,32,64,96
    const int lm = lane >> 3;           // ldmatrix matrix id
    const int lr = lane & 7;            // row within matrix
    const int arowA = mA + ((lm & 1) << 3) + lr;
    const int koff = (lm >> 1) << 3;

    // prologue: load chunk 0 fragments
    uint4 cur[4];
#pragma unroll
    for (int p = 0; p < 4; p++) cur[p] = load_frag(in, blk0 + rs[p], cs);

#pragma unroll
    for (int chunk = 0; chunk < 2; chunk++) {
        const int row0 = blk0 + chunk * 64;
        __syncthreads();   // sA free (prev readers done); also covers W stage
#pragma unroll
        for (int p = 0; p < 4; p++)
            *reinterpret_cast<uint4*>(&sA[rs[p] * SA_STRIDE + cs]) = cur[p];
        if (chunk == 0) {  // prefetch chunk 1; overlaps chunk 0 MMA below
#pragma unroll
            for (int p = 0; p < 4; p++) cur[p] = load_frag(in, row0 + 64 + rs[p], cs);
        }
        __syncthreads();

        float4 cA[4], cB[4];
#pragma unroll
        for (int j = 0; j < 4; j++) {
            cA[j] = make_float4(0.f, 0.f, 0.f, 0.f);
            cB[j] = make_float4(0.f, 0.f, 0.f, 0.f);
        }

#pragma unroll
        for (int ks = 0; ks < 8; ks++) {
            int k0 = ks << 4;
            unsigned aA0, aA1, aA2, aA3, aB0, aB1, aB2, aB3;
            ldsm_x4(aA0, aA1, aA2, aA3, smem_u32(&sA[arowA * SA_STRIDE + k0 + koff]));
            ldsm_x4(aB0, aB1, aB2, aB3, smem_u32(&sA[(arowA + 32) * SA_STRIDE + k0 + koff]));
#pragma unroll
            for (int j = 0; j < 2; j++) {
                int n = n0 + (j << 4);
                unsigned b0, b1, b2, b3;
                ldsm_x4_t(b0, b1, b2, b3,
                          smem_u32(&sW[(k0 + ((lm & 1) << 3) + lr) * SW_STRIDE + n + koff]));
                mma16816(cA[2 * j],     aA0, aA1, aA2, aA3, b0, b1);
                mma16816(cA[2 * j + 1], aA0, aA1, aA2, aA3, b2, b3);
                mma16816(cB[2 * j],     aB0, aB1, aB2, aB3, b0, b1);
                mma16816(cB[2 * j + 1], aB0, aB1, aB2, aB3, b2, b3);
            }
        }

        // epilogue: scale by norm_src, convert fp16, store (both m-tiles)
#pragma unroll
        for (int t = 0; t < 2; t++) {
            float4* cc = (t == 0) ? cA : cB;
            const int r0 = row0 + mA + t * 32 + (lane >> 2);
            const int r1 = r0 + 8;
            float ns0 = (r0 < NN) ? g_nsrc[r0] : 0.f;
            float ns1 = (r1 < NN) ? g_nsrc[r1] : 0.f;
#pragma unroll
            for (int j = 0; j < 4; j++) {
                int col = n0 + (j << 3) + ((lane & 3) << 1);
                if (r0 < NN) {
                    __half2 h = __floats2half2_rn(cc[j].x * ns0, cc[j].y * ns0);
                    *reinterpret_cast<__half2*>(out + (size_t)r0 * FD + col) = h;
                }
                if (r1 < NN) {
                    __half2 h = __floats2half2_rn(cc[j].z * ns1, cc[j].w * ns1);
                    *reinterpret_cast<__half2*>(out + (size_t)r1 * FD + col) = h;
                }
            }
        }
    }
}

// ---- warp-per-node CSR accumulate over fp16 rows (fp32 accum), unroll-4 ----
__device__ __forceinline__ float4 csr_accum(int node, int lane) {
    int beg = g_rowptr[node];
    int end = g_rowptr[node + 1];
    float4 acc = make_float4(0.f, 0.f, 0.f, 0.f);
    int j = beg;
    for (; j + 4 <= end; j += 4) {
        int s0 = __ldg(g_csr + j);
        int s1 = __ldg(g_csr + j + 1);
        int s2 = __ldg(g_csr + j + 2);
        int s3 = __ldg(g_csr + j + 3);
        uint2 u0 = *reinterpret_cast<const uint2*>(g_hh + (size_t)s0 * FD + lane * 4);
        uint2 u1 = *reinterpret_cast<const uint2*>(g_hh + (size_t)s1 * FD + lane * 4);
        uint2 u2 = *reinterpret_cast<const uint2*>(g_hh + (size_t)s2 * FD + lane * 4);
        uint2 u3 = *reinterpret_cast<const uint2*>(g_hh + (size_t)s3 * FD + lane * 4);
        float2 a0 = __half22float2(*reinterpret_cast<__half2*>(&u0.x));
        float2 b0 = __half22float2(*reinterpret_cast<__half2*>(&u0.y));
        float2 a1 = __half22float2(*reinterpret_cast<__half2*>(&u1.x));
        float2 b1 = __half22float2(*reinterpret_cast<__half2*>(&u1.y));
        float2 a2 = __half22float2(*reinterpret_cast<__half2*>(&u2.x));
        float2 b2 = __half22float2(*reinterpret_cast<__half2*>(&u2.y));
        float2 a3 = __half22float2(*reinterpret_cast<__half2*>(&u3.x));
        float2 b3 = __half22float2(*reinterpret_cast<__half2*>(&u3.y));
        acc.x += (a0.x + a1.x) + (a2.x + a3.x);
        acc.y += (a0.y + a1.y) + (a2.y + a3.y);
        acc.z += (b0.x + b1.x) + (b2.x + b3.x);
        acc.w += (b0.y + b1.y) + (b2.y + b3.y);
    }
    for (; j < end; j++) {
        int s = __ldg(g_csr + j);
        uint2 u = *reinterpret_cast<const uint2*>(g_hh + (size_t)s * FD + lane * 4);
        float2 a = __half22float2(*reinterpret_cast<__half2*>(&u.x));
        float2 b = __half22float2(*reinterpret_cast<__half2*>(&u.y));
        acc.x += a.x; acc.y += a.y; acc.z += b.x; acc.w += b.y;
    }
    return acc;
}

// ---- layer 1 aggregate, fused epilogue: z = fp16(relu(agg*nd + b1)) ----
__global__ __launch_bounds__(256) void gather1_k(const float* __restrict__ b1) {
    int w = (blockIdx.x * 256 + threadIdx.x) >> 5;
    if (w >= NN) return;
    int lane = threadIdx.x & 31;
    float4 acc = csr_accum(w, lane);
    float nd = g_ndst[w];
    float4 b = __ldg(reinterpret_cast<const float4*>(b1 + lane * 4));
    float ox = fmaxf(fmaf(acc.x, nd, b.x), 0.f);
    float oy = fmaxf(fmaf(acc.y, nd, b.y), 0.f);
    float oz = fmaxf(fmaf(acc.z, nd, b.z), 0.f);
    float ow = fmaxf(fmaf(acc.w, nd, b.w), 0.f);
    __half2 h01 = __floats2half2_rn(ox, oy);
    __half2 h23 = __floats2half2_rn(oz, ow);
    uint2 st;
    st.x = *reinterpret_cast<unsigned*>(&h01);
    st.y = *reinterpret_cast<unsigned*>(&h23);
    *reinterpret_cast<uint2*>(g_zh + (size_t)w * FD + lane * 4) = st;
}

// ---- layer 2 aggregate, fused link-predictor projection: a[i], c[i] ----
__global__ __launch_bounds__(256) void gather2_k(const float* __restrict__ b2,
                                                 const float* __restrict__ Wp) {
    int w = (blockIdx.x * 256 + threadIdx.x) >> 5;
    if (w >= NN) return;
    int lane = threadIdx.x & 31;
    float4 acc = csr_accum(w, lane);
    float nd = g_ndst[w];
    float4 b  = __ldg(reinterpret_cast<const float4*>(b2 + lane * 4));
    float4 w1 = __ldg(reinterpret_cast<const float4*>(Wp + lane * 4));
    float4 w2 = __ldg(reinterpret_cast<const float4*>(Wp + FD + lane * 4));
    float hx = fmaf(acc.x, nd, b.x);
    float hy = fmaf(acc.y, nd, b.y);
    float hz = fmaf(acc.z, nd, b.z);
    float hw = fmaf(acc.w, nd, b.w);
    float av = hx * w1.x + hy * w1.y + hz * w1.z + hw * w1.w;
    float cv = hx * w2.x + hy * w2.y + hz * w2.z + hw * w2.w;
#pragma unroll
    for (int off = 16; off > 0; off >>= 1) {
        av += __shfl_xor_sync(0xffffffffu, av, off);
        cv += __shfl_xor_sync(0xffffffffu, cv, off);
    }
    if (lane == 0) { g_a[w] = av; g_c[w] = cv; }
}

// ---- final per-edge score: sigmoid(a[src] + c[dst] + bp) ----
__global__ void edgescore_k(const int* __restrict__ src, const int* __restrict__ dst,
                            const float* __restrict__ bp, float* __restrict__ out) {
    int e = blockIdx.x * blockDim.x + threadIdx.x;
    if (e < NE) {
        float z = g_a[__ldg(src + e)] + g_c[__ldg(dst + e)] + __ldg(bp);
        out[e] = 1.0f / (1.0f + expf(-z));
    }
}

extern "C" void kernel_launch(void* const* d_in, const int* in_sizes, int n_in,
                              void* d_out, int out_size) {
    (void)in_sizes; (void)n_in; (void)out_size;
    const float* x  = (const float*)d_in[0];
    const float* W1 = (const float*)d_in[1];
    const float* b1 = (const float*)d_in[2];
    const float* W2 = (const float*)d_in[3];
    const float* b2 = (const float*)d_in[4];
    const float* Wp = (const float*)d_in[5];
    const float* bp = (const float*)d_in[6];
    const int* src  = (const int*)d_in[7];
    const int* dst  = (const int*)d_in[8];
    float* out = (float*)d_out;

    void *p_hh, *p_zh, *p_w1, *p_w2, *p_di, *p_do;
    cudaGetSymbolAddress(&p_hh, g_hh);
    cudaGetSymbolAddress(&p_zh, g_zh);
    cudaGetSymbolAddress(&p_w1, g_Wh1);
    cudaGetSymbolAddress(&p_w2, g_Wh2);
    cudaGetSymbolAddress(&p_di, g_degin);
    cudaGetSymbolAddress(&p_do, g_degout);

    cudaMemsetAsync(p_di, 0, sizeof(int) * NN);
    cudaMemsetAsync(p_do, 0, sizeof(int) * NN);

    // degrees + norms + W1, then GEMM1 (launch #6 -> profiled by -s 5 -c 1)
    count_k<<<(NE + 255) / 256, 256>>>(src, dst);
    norm_k<<<(NN + 255) / 256, 256>>>();
    packW_k<<<(FD * FD + 255) / 256, 256>>>(W1, (__half*)p_w1);
    gemm_k<float><<<(NN + ROWS_PER_BLK - 1) / ROWS_PER_BLK, 256>>>(
        x, (const __half*)p_w1, (__half*)p_hh);

    // CSR (dst-bucketed) build
    blocksum_k<<<NB, 256>>>();
    scanbsum_k<<<1, 512>>>();
    rowptr_k<<<NB, 256>>>();
    fill_k<<<(NE + 255) / 256, 256>>>(src, dst);

    // Layer 1 aggregate: z = fp16(relu(agg1 * norm_dst + b1))
    gather1_k<<<(NN * 32 + 255) / 256, 256>>>(b1);

    // Layer 2: h = fp16((z @ W2) * norm_src) ; fused gather -> per-node a, c
    packW_k<<<(FD * FD + 255) / 256, 256>>>(W2, (__half*)p_w2);
    gemm_k<__half><<<(NN + ROWS_PER_BLK - 1) / ROWS_PER_BLK, 256>>>(
        (const __half*)p_zh, (const __half*)p_w2, (__half*)p_hh);
    gather2_k<<<(NN * 32 + 255) / 256, 256>>>(b2, Wp);

    // Per-edge score
    edgescore_k<<<(NE + 255) / 256, 256>>>(src, dst, bp, out);
}

// round 13
// speedup vs baseline: 1.6989x; 1.2182x over previous
#include <cuda_runtime.h>
#include <cuda_fp16.h>

#define NN 100000
#define NE 1600000
#define FD 128
#define NB 391            // ceil(NN / 256)
#define SA_STRIDE 136     // 128 + 8 halves pad -> conflict-free ldmatrix
#define SW_STRIDE 136
#define ROWS_PER_BLK 128  // 2 chunks of 64 rows; W staged once per block

// ---- scratch (static device arrays; no runtime alloc allowed) ----
static __device__ __half g_hh[(size_t)NN * FD];   // layer-1 post-GEMM features (fp16)
static __device__ __half g_Wh1[FD * FD];          // W1 in fp16
static __device__ int    g_degout[NN];
static __device__ int    g_degin[NN];
static __device__ float  g_nsrc[NN];
static __device__ float  g_ndst[NN];
static __device__ int    g_rowptr[NN + 1];
static __device__ int    g_cursor[NN];
static __device__ int    g_csr[NE];               // src ids bucketed by dst
static __device__ int    g_bsum[512];
static __device__ float  g_u1[FD];                // W2 @ Wp[:128]
static __device__ float  g_u2[FD];                // W2 @ Wp[128:]
static __device__ float  g_cA, g_cB;              // dot(b2,Wp1), dot(b2,Wp2)
static __device__ float2 g_pq[NN];                // per-node {p,q} projections
static __device__ float  g_a[NN];                 // src-side edge scalar
static __device__ float  g_c[NN];                 // dst-side edge scalar

// ---- degree counting ----
__global__ void count_k(const int* __restrict__ src, const int* __restrict__ dst) {
    int e = blockIdx.x * blockDim.x + threadIdx.x;
    if (e < NE) {
        atomicAdd(&g_degout[src[e]], 1);
        atomicAdd(&g_degin[dst[e]], 1);
    }
}

__global__ void norm_k() {
    int i = blockIdx.x * blockDim.x + threadIdx.x;
    if (i < NN) {
        g_nsrc[i] = rsqrtf(fmaxf((float)g_degout[i], 1.0f));
        g_ndst[i] = rsqrtf(fmaxf((float)g_degin[i], 1.0f));
    }
}

// ---- W fp32 -> fp16 ----
__global__ void packW_k(const float* __restrict__ W, __half* __restrict__ Wh) {
    int i = blockIdx.x * blockDim.x + threadIdx.x;
    if (i < FD * FD) Wh[i] = __float2half(__ldg(W + i));
}

// ---- layer-2 collapse precompute: u1 = W2@Wp1, u2 = W2@Wp2, cA, cB ----
__global__ void prep_k(const float* __restrict__ W2, const float* __restrict__ Wp,
                       const float* __restrict__ b2) {
    int t = threadIdx.x;   // 128 threads, one input-row each
    float s1 = 0.f, s2 = 0.f;
#pragma unroll 4
    for (int o = 0; o < FD; o++) {
        float w = __ldg(W2 + t * FD + o);
        s1 += w * __ldg(Wp + o);
        s2 += w * __ldg(Wp + FD + o);
    }
    g_u1[t] = s1;
    g_u2[t] = s2;

    // cA = dot(b2, Wp1), cB = dot(b2, Wp2)
    float bv = __ldg(b2 + t);
    float c1 = bv * __ldg(Wp + t);
    float c2 = bv * __ldg(Wp + FD + t);
    __shared__ float sh1[128], sh2[128];
    sh1[t] = c1; sh2[t] = c2;
    __syncthreads();
    for (int off = 64; off > 0; off >>= 1) {
        if (t < off) { sh1[t] += sh1[t + off]; sh2[t] += sh2[t + off]; }
        __syncthreads();
    }
    if (t == 0) { g_cA = sh1[0]; g_cB = sh2[0]; }
}

// ---- CSR build ----
__global__ void blocksum_k() {
    int i = blockIdx.x * 256 + threadIdx.x;
    int v = (i < NN) ? g_degin[i] : 0;
#pragma unroll
    for (int off = 16; off > 0; off >>= 1) v += __shfl_xor_sync(0xffffffffu, v, off);
    __shared__ int s[8];
    int lane = threadIdx.x & 31, wid = threadIdx.x >> 5;
    if (lane == 0) s[wid] = v;
    __syncthreads();
    if (threadIdx.x == 0) {
        int t = 0;
#pragma unroll
        for (int w = 0; w < 8; w++) t += s[w];
        g_bsum[blockIdx.x] = t;
    }
}

__global__ void scanbsum_k() {   // single block, exclusive scan of NB block sums
    __shared__ int sh[512];
    int t = threadIdx.x;
    int v = (t < NB) ? g_bsum[t] : 0;
    sh[t] = v;
    __syncthreads();
    for (int off = 1; off < 512; off <<= 1) {
        int a = (t >= off) ? sh[t - off] : 0;
        __syncthreads();
        sh[t] += a;
        __syncthreads();
    }
    if (t < NB) g_bsum[t] = sh[t] - v;   // exclusive
}

__global__ void rowptr_k() {
    int i = blockIdx.x * 256 + threadIdx.x;
    int lane = threadIdx.x & 31, wid = threadIdx.x >> 5;
    int v = (i < NN) ? g_degin[i] : 0;
    int incl = v;
#pragma unroll
    for (int off = 1; off < 32; off <<= 1) {
        int n = __shfl_up_sync(0xffffffffu, incl, off);
        if (lane >= off) incl += n;
    }
    __shared__ int ws[8];
    if (lane == 31) ws[wid] = incl;
    __syncthreads();
    if (threadIdx.x == 0) {
        int run = 0;
#pragma unroll
        for (int w = 0; w < 8; w++) { int t = ws[w]; ws[w] = run; run += t; }
    }
    __syncthreads();
    int excl = incl - v + ws[wid] + g_bsum[blockIdx.x];
    if (i < NN) {
        g_rowptr[i] = excl;
        g_cursor[i] = excl;
        if (i == NN - 1) g_rowptr[NN] = excl + v;
    }
}

__global__ void fill_k(const int* __restrict__ src, const int* __restrict__ dst) {
    int e = blockIdx.x * blockDim.x + threadIdx.x;
    if (e < NE) {
        int d = dst[e];
        int pos = atomicAdd(&g_cursor[d], 1);
        g_csr[pos] = src[e];
    }
}

// ---- HMMA helpers ----
__device__ __forceinline__ unsigned smem_u32(const void* p) {
    return (unsigned)__cvta_generic_to_shared(p);
}

__device__ __forceinline__ void ldsm_x4(unsigned& r0, unsigned& r1, unsigned& r2,
                                        unsigned& r3, unsigned addr) {
    asm volatile("ldmatrix.sync.aligned.m8n8.x4.shared.b16 {%0,%1,%2,%3}, [%4];"
                 : "=r"(r0), "=r"(r1), "=r"(r2), "=r"(r3) : "r"(addr));
}

__device__ __forceinline__ void ldsm_x4_t(unsigned& r0, unsigned& r1, unsigned& r2,
                                          unsigned& r3, unsigned addr) {
    asm volatile("ldmatrix.sync.aligned.m8n8.x4.trans.shared.b16 {%0,%1,%2,%3}, [%4];"
                 : "=r"(r0), "=r"(r1), "=r"(r2), "=r"(r3) : "r"(addr));
}

__device__ __forceinline__ void mma16816(float4& c, unsigned a0, unsigned a1,
                                         unsigned a2, unsigned a3,
                                         unsigned b0, unsigned b1) {
    asm volatile("mma.sync.aligned.m16n8k16.row.col.f32.f16.f16.f32 "
                 "{%0,%1,%2,%3}, {%4,%5,%6,%7}, {%8,%9}, {%0,%1,%2,%3};"
                 : "+f"(c.x), "+f"(c.y), "+f"(c.z), "+f"(c.w)
                 : "r"(a0), "r"(a1), "r"(a2), "r"(a3), "r"(b0), "r"(b1));
}

// ---- fp32 row-fragment load -> 8 fp16 cols packed in uint4 ----
__device__ __forceinline__ uint4 load_frag(const float* __restrict__ in, int gr, int c8) {
    uint4 st = make_uint4(0u, 0u, 0u, 0u);
    if (gr < NN) {
        float4 f0 = *reinterpret_cast<const float4*>(in + (size_t)gr * FD + c8);
        float4 f1 = *reinterpret_cast<const float4*>(in + (size_t)gr * FD + c8 + 4);
        __half2 h0 = __floats2half2_rn(f0.x, f0.y);
        __half2 h1 = __floats2half2_rn(f0.z, f0.w);
        __half2 h2 = __floats2half2_rn(f1.x, f1.y);
        __half2 h3 = __floats2half2_rn(f1.z, f1.w);
        st.x = *reinterpret_cast<unsigned*>(&h0);
        st.y = *reinterpret_cast<unsigned*>(&h1);
        st.z = *reinterpret_cast<unsigned*>(&h2);
        st.w = *reinterpret_cast<unsigned*>(&h3);
    }
    return st;
}

// ---- GEMM1: out[i][:] = fp16( norm_src[i] * (x[i][:] @ W1) ), tensor cores ----
// 256 thr / 8 warps, 128 rows in 2 chunks of 64; W staged once per block.
// Per-chunk register prefetch overlaps DRAM; each warp computes two m=16
// tiles per chunk sharing B fragments.
__global__ __launch_bounds__(256) void gemm_k(const float* __restrict__ in,
                                              const __half* __restrict__ Wh,
                                              __half* __restrict__ out) {
    __shared__ __half sA[64 * SA_STRIDE];
    __shared__ __half sW[FD * SW_STRIDE];
    const int tid = threadIdx.x;
    const int blk0 = blockIdx.x * ROWS_PER_BLK;

    for (int i = tid; i < FD * 16; i += 256) {
        int r = i >> 4;
        int c8 = (i & 15) << 3;
        uint4 v = *reinterpret_cast<const uint4*>(Wh + r * FD + c8);
        *reinterpret_cast<uint4*>(&sW[r * SW_STRIDE + c8]) = v;
    }

    int rs[4];
    const int cs = (tid & 15) << 3;
#pragma unroll
    for (int p = 0; p < 4; p++) rs[p] = (tid + p * 256) >> 4;

    const int lane = tid & 31;
    const int wid = tid >> 5;
    const int mA = (wid & 1) << 4;
    const int n0 = (wid >> 1) << 5;
    const int lm = lane >> 3;
    const int lr = lane & 7;
    const int arowA = mA + ((lm & 1) << 3) + lr;
    const int koff = (lm >> 1) << 3;

    uint4 cur[4];
#pragma unroll
    for (int p = 0; p < 4; p++) cur[p] = load_frag(in, blk0 + rs[p], cs);

#pragma unroll
    for (int chunk = 0; chunk < 2; chunk++) {
        const int row0 = blk0 + chunk * 64;
        __syncthreads();
#pragma unroll
        for (int p = 0; p < 4; p++)
            *reinterpret_cast<uint4*>(&sA[rs[p] * SA_STRIDE + cs]) = cur[p];
        if (chunk == 0) {
#pragma unroll
            for (int p = 0; p < 4; p++) cur[p] = load_frag(in, row0 + 64 + rs[p], cs);
        }
        __syncthreads();

        float4 cA[4], cB[4];
#pragma unroll
        for (int j = 0; j < 4; j++) {
            cA[j] = make_float4(0.f, 0.f, 0.f, 0.f);
            cB[j] = make_float4(0.f, 0.f, 0.f, 0.f);
        }

#pragma unroll
        for (int ks = 0; ks < 8; ks++) {
            int k0 = ks << 4;
            unsigned aA0, aA1, aA2, aA3, aB0, aB1, aB2, aB3;
            ldsm_x4(aA0, aA1, aA2, aA3, smem_u32(&sA[arowA * SA_STRIDE + k0 + koff]));
            ldsm_x4(aB0, aB1, aB2, aB3, smem_u32(&sA[(arowA + 32) * SA_STRIDE + k0 + koff]));
#pragma unroll
            for (int j = 0; j < 2; j++) {
                int n = n0 + (j << 4);
                unsigned b0, b1, b2, b3;
                ldsm_x4_t(b0, b1, b2, b3,
                          smem_u32(&sW[(k0 + ((lm & 1) << 3) + lr) * SW_STRIDE + n + koff]));
                mma16816(cA[2 * j],     aA0, aA1, aA2, aA3, b0, b1);
                mma16816(cA[2 * j + 1], aA0, aA1, aA2, aA3, b2, b3);
                mma16816(cB[2 * j],     aB0, aB1, aB2, aB3, b0, b1);
                mma16816(cB[2 * j + 1], aB0, aB1, aB2, aB3, b2, b3);
            }
        }

#pragma unroll
        for (int t = 0; t < 2; t++) {
            float4* cc = (t == 0) ? cA : cB;
            const int r0 = row0 + mA + t * 32 + (lane >> 2);
            const int r1 = r0 + 8;
            float ns0 = (r0 < NN) ? g_nsrc[r0] : 0.f;
            float ns1 = (r1 < NN) ? g_nsrc[r1] : 0.f;
#pragma unroll
            for (int j = 0; j < 4; j++) {
                int col = n0 + (j << 3) + ((lane & 3) << 1);
                if (r0 < NN) {
                    __half2 h = __floats2half2_rn(cc[j].x * ns0, cc[j].y * ns0);
                    *reinterpret_cast<__half2*>(out + (size_t)r0 * FD + col) = h;
                }
                if (r1 < NN) {
                    __half2 h = __floats2half2_rn(cc[j].z * ns1, cc[j].w * ns1);
                    *reinterpret_cast<__half2*>(out + (size_t)r1 * FD + col) = h;
                }
            }
        }
    }
}

// ---- warp-per-node CSR accumulate over fp16 rows (fp32 accum), unroll-4 ----
__device__ __forceinline__ float4 csr_accum(int node, int lane) {
    int beg = g_rowptr[node];
    int end = g_rowptr[node + 1];
    float4 acc = make_float4(0.f, 0.f, 0.f, 0.f);
    int j = beg;
    for (; j + 4 <= end; j += 4) {
        int s0 = __ldg(g_csr + j);
        int s1 = __ldg(g_csr + j + 1);
        int s2 = __ldg(g_csr + j + 2);
        int s3 = __ldg(g_csr + j + 3);
        uint2 u0 = *reinterpret_cast<const uint2*>(g_hh + (size_t)s0 * FD + lane * 4);
        uint2 u1 = *reinterpret_cast<const uint2*>(g_hh + (size_t)s1 * FD + lane * 4);
        uint2 u2 = *reinterpret_cast<const uint2*>(g_hh + (size_t)s2 * FD + lane * 4);
        uint2 u3 = *reinterpret_cast<const uint2*>(g_hh + (size_t)s3 * FD + lane * 4);
        float2 a0 = __half22float2(*reinterpret_cast<__half2*>(&u0.x));
        float2 b0 = __half22float2(*reinterpret_cast<__half2*>(&u0.y));
        float2 a1 = __half22float2(*reinterpret_cast<__half2*>(&u1.x));
        float2 b1 = __half22float2(*reinterpret_cast<__half2*>(&u1.y));
        float2 a2 = __half22float2(*reinterpret_cast<__half2*>(&u2.x));
        float2 b2 = __half22float2(*reinterpret_cast<__half2*>(&u2.y));
        float2 a3 = __half22float2(*reinterpret_cast<__half2*>(&u3.x));
        float2 b3 = __half22float2(*reinterpret_cast<__half2*>(&u3.y));
        acc.x += (a0.x + a1.x) + (a2.x + a3.x);
        acc.y += (a0.y + a1.y) + (a2.y + a3.y);
        acc.z += (b0.x + b1.x) + (b2.x + b3.x);
        acc.w += (b0.y + b1.y) + (b2.y + b3.y);
    }
    for (; j < end; j++) {
        int s = __ldg(g_csr + j);
        uint2 u = *reinterpret_cast<const uint2*>(g_hh + (size_t)s * FD + lane * 4);
        float2 a = __half22float2(*reinterpret_cast<__half2*>(&u.x));
        float2 b = __half22float2(*reinterpret_cast<__half2*>(&u.y));
        acc.x += a.x; acc.y += a.y; acc.z += b.x; acc.w += b.y;
    }
    return acc;
}

// ---- layer-1 aggregate + FUSED layer-2 projection:
// z = relu(agg*nd + b1)  (in registers only)
// p[w] = nsrc[w]*dot(z,u1), q[w] = nsrc[w]*dot(z,u2)  -> g_pq ----
__global__ __launch_bounds__(256) void gather1_k(const float* __restrict__ b1) {
    int w = (blockIdx.x * 256 + threadIdx.x) >> 5;
    if (w >= NN) return;
    int lane = threadIdx.x & 31;
    float4 acc = csr_accum(w, lane);
    float nd = g_ndst[w];
    float4 b = __ldg(reinterpret_cast<const float4*>(b1 + lane * 4));
    float zx = fmaxf(fmaf(acc.x, nd, b.x), 0.f);
    float zy = fmaxf(fmaf(acc.y, nd, b.y), 0.f);
    float zz = fmaxf(fmaf(acc.z, nd, b.z), 0.f);
    float zw = fmaxf(fmaf(acc.w, nd, b.w), 0.f);
    float4 U1 = *reinterpret_cast<const float4*>(g_u1 + lane * 4);
    float4 U2 = *reinterpret_cast<const float4*>(g_u2 + lane * 4);
    float pv = zx * U1.x + zy * U1.y + zz * U1.z + zw * U1.w;
    float qv = zx * U2.x + zy * U2.y + zz * U2.z + zw * U2.w;
#pragma unroll
    for (int off = 16; off > 0; off >>= 1) {
        pv += __shfl_xor_sync(0xffffffffu, pv, off);
        qv += __shfl_xor_sync(0xffffffffu, qv, off);
    }
    if (lane == 0) {
        float ns = g_nsrc[w];
        g_pq[w] = make_float2(ns * pv, ns * qv);
    }
}

// ---- layer-2 scalar aggregate: a[i] = nd[i]*Sum p[j] + cA (thread/node) ----
__global__ __launch_bounds__(256) void gather2s_k() {
    int i = blockIdx.x * 256 + threadIdx.x;
    if (i >= NN) return;
    int beg = g_rowptr[i];
    int end = g_rowptr[i + 1];
    float sp = 0.f, sq = 0.f;
    int j = beg;
    for (; j + 4 <= end; j += 4) {
        int s0 = __ldg(g_csr + j);
        int s1 = __ldg(g_csr + j + 1);
        int s2 = __ldg(g_csr + j + 2);
        int s3 = __ldg(g_csr + j + 3);
        float2 v0 = g_pq[s0];
        float2 v1 = g_pq[s1];
        float2 v2 = g_pq[s2];
        float2 v3 = g_pq[s3];
        sp += (v0.x + v1.x) + (v2.x + v3.x);
        sq += (v0.y + v1.y) + (v2.y + v3.y);
    }
    for (; j < end; j++) {
        float2 v = g_pq[__ldg(g_csr + j)];
        sp += v.x; sq += v.y;
    }
    float nd = g_ndst[i];
    g_a[i] = fmaf(nd, sp, g_cA);
    g_c[i] = fmaf(nd, sq, g_cB);
}

// ---- final per-edge score: sigmoid(a[src] + c[dst] + bp) ----
__global__ void edgescore_k(const int* __restrict__ src, const int* __restrict__ dst,
                            const float* __restrict__ bp, float* __restrict__ out) {
    int e = blockIdx.x * blockDim.x + threadIdx.x;
    if (e < NE) {
        float z = g_a[__ldg(src + e)] + g_c[__ldg(dst + e)] + __ldg(bp);
        out[e] = 1.0f / (1.0f + expf(-z));
    }
}

extern "C" void kernel_launch(void* const* d_in, const int* in_sizes, int n_in,
                              void* d_out, int out_size) {
    (void)in_sizes; (void)n_in; (void)out_size;
    const float* x  = (const float*)d_in[0];
    const float* W1 = (const float*)d_in[1];
    const float* b1 = (const float*)d_in[2];
    const float* W2 = (const float*)d_in[3];
    const float* b2 = (const float*)d_in[4];
    const float* Wp = (const float*)d_in[5];
    const float* bp = (const float*)d_in[6];
    const int* src  = (const int*)d_in[7];
    const int* dst  = (const int*)d_in[8];
    float* out = (float*)d_out;

    void *p_hh, *p_w1, *p_di, *p_do;
    cudaGetSymbolAddress(&p_hh, g_hh);
    cudaGetSymbolAddress(&p_w1, g_Wh1);
    cudaGetSymbolAddress(&p_di, g_degin);
    cudaGetSymbolAddress(&p_do, g_degout);

    cudaMemsetAsync(p_di, 0, sizeof(int) * NN);
    cudaMemsetAsync(p_do, 0, sizeof(int) * NN);

    // degrees + norms + W1, then GEMM1 (launch #6 -> profiled by -s 5 -c 1)
    count_k<<<(NE + 255) / 256, 256>>>(src, dst);
    norm_k<<<(NN + 255) / 256, 256>>>();
    packW_k<<<(FD * FD + 255) / 256, 256>>>(W1, (__half*)p_w1);
    gemm_k<<<(NN + ROWS_PER_BLK - 1) / ROWS_PER_BLK, 256>>>(
        x, (const __half*)p_w1, (__half*)p_hh);

    // CSR (dst-bucketed) build + layer-2 collapse precompute
    blocksum_k<<<NB, 256>>>();
    scanbsum_k<<<1, 512>>>();
    rowptr_k<<<NB, 256>>>();
    fill_k<<<(NE + 255) / 256, 256>>>(src, dst);
    prep_k<<<1, 128>>>(W2, Wp, b2);

    // Layer 1 aggregate + fused layer-2 projection -> p,q per node
    gather1_k<<<(NN * 32 + 255) / 256, 256>>>(b1);

    // Layer 2 scalar aggregate -> a,c per node
    gather2s_k<<<(NN + 255) / 256, 256>>>();

    // Per-edge score
    edgescore_k<<<(NE + 255) / 256, 256>>>(src, dst, bp, out);
}